// round 12
// baseline (speedup 1.0000x reference)
#include <cuda_runtime.h>
#include <cuda_bf16.h>
#include <cstdint>

// DifferentiableSelector, persistent + TMA, tanh-based sigmoid (3 ops/elem).
//  R10 post-mortem: kernel is ISSUE-bound (three different memory structures
//  all ~28us; DRAM 34%). sigmoid(z) = 0.5*tanh(z/2)+0.5 cuts per-element
//  cost from ~11 ops (ex2 + Newton reciprocal) to 3 (FMUL+MUFU+FFMA).
//  Identity-damping proof hardened for the approximation: raw-score max
//  (monotone) -> ymax bound + 2e-3 margin; 2*scale*ymax_bound <= 1 implies
//  every damping factor min(2/(1+a+b),1) == 1 for the COMPUTED y values.
//  Exact chunked slow path retained for arbitrary inputs.

static constexpr int   T_DIM = 32768;
static constexpr int   NT    = 1024;
static constexpr int   VPT   = T_DIM / NT / 4;   // 8 float4 per thread
static constexpr int   GRID  = 128;              // 512 rows / 128 = 4 rows/CTA
static constexpr float K_SEL = 64.0f;
static constexpr int   BUF_BYTES = T_DIM * 4;    // 128 KB row buffer

// slow-path chunking: 4 chunks of 8192 elements, halo 10 (use 12 = 3 float4)
static constexpr int CHUNK = 8192;
static constexpr int CPT   = CHUNK / NT;         // 8 contiguous elems/thread
static constexpr int DYN_SMEM = BUF_BYTES + (CHUNK + 12) * 4;   // 163888 B

__device__ __forceinline__ float tanh_approx(float x) {
    float r; asm("tanh.approx.f32 %0, %1;" : "=f"(r) : "f"(x)); return r;
}
__device__ __forceinline__ uint32_t smem_u32(const void* p) {
    uint32_t a;
    asm("{ .reg .u64 t; cvta.to.shared.u64 t, %1; cvt.u32.u64 %0, t; }"
        : "=r"(a) : "l"(p));
    return a;
}
__device__ __forceinline__ void mbar_init(uint32_t mbar, uint32_t cnt) {
    asm volatile("mbarrier.init.shared.b64 [%0], %1;" :: "r"(mbar), "r"(cnt) : "memory");
}
__device__ __forceinline__ void mbar_expect_tx(uint32_t mbar, uint32_t bytes) {
    asm volatile("mbarrier.arrive.expect_tx.shared.b64 _, [%0], %1;"
                 :: "r"(mbar), "r"(bytes) : "memory");
}
__device__ __forceinline__ void bulk_ld(uint32_t dst_smem, const void* src,
                                        uint32_t bytes, uint32_t mbar) {
    asm volatile(
        "cp.async.bulk.shared::cta.global.mbarrier::complete_tx::bytes [%0], [%1], %2, [%3];"
        :: "r"(dst_smem), "l"(src), "r"(bytes), "r"(mbar) : "memory");
}
__device__ __forceinline__ void mbar_wait(uint32_t mbar, uint32_t parity) {
    asm volatile(
        "{\n\t"
        ".reg .pred P;\n\t"
        "WAIT_%=:\n\t"
        "mbarrier.try_wait.parity.acquire.cta.shared::cta.b64 P, [%0], %1, 0x989680;\n\t"
        "@P bra.uni DONE_%=;\n\t"
        "bra.uni WAIT_%=;\n\t"
        "DONE_%=:\n\t"
        "}" :: "r"(mbar), "r"(parity) : "memory");
}

// sigmoid(x*invt) = 0.5*tanh(x*invt/2) + 0.5 : 1 FMUL + 1 MUFU + 1 FFMA.
__device__ __forceinline__ float sigt(float x, float ch) {
    return fmaf(0.5f, tanh_approx(x * ch), 0.5f);
}

__global__ __launch_bounds__(NT, 1)
void fused_tanh(const float* __restrict__ scores,
                const float* __restrict__ log_temp,
                float* __restrict__ out, int B)
{
    extern __shared__ __align__(16) float dsm[];
    float4* buf4 = reinterpret_cast<float4*>(dsm);          // 128 KB row buffer
    float*  ys   = dsm + T_DIM;                             // slow-path staging
    __shared__ float reds[32], redm[32];
    __shared__ float s_scale;
    __shared__ int   s_fast;
    __shared__ __align__(8) uint64_t mbar_storage;

    const int tid = threadIdx.x;
    const uint32_t mbar = smem_u32(&mbar_storage);
    const uint32_t bufa = smem_u32(dsm);

    float temp = __expf(log_temp[0]);
    temp = fminf(fmaxf(temp, 0.1f), 10.0f);
    const float ch = __fdividef(0.5f, temp);     // tanh argument scale

    int r = blockIdx.x;                          // grid <= B by launcher
    if (tid == 0) mbar_init(mbar, 1);
    __syncthreads();
    if (tid == 0) {
        mbar_expect_tx(mbar, BUF_BYTES);
        bulk_ld(bufa, scores + (size_t)r * T_DIM, BUF_BYTES, mbar);
    }
    uint32_t parity = 0;

    while (true) {
        // ---- wait TMA, read row from smem, sigmoid (3 ops), sum + raw max ----
        mbar_wait(mbar, parity);
        float4 v[VPT];
#pragma unroll
        for (int k = 0; k < VPT; ++k) v[k] = buf4[tid + k * NT];

        float mxx = -3.4e38f;                    // raw-score max (monotone)
#pragma unroll
        for (int k = 0; k < VPT; ++k)
            mxx = fmaxf(mxx, fmaxf(fmaxf(v[k].x, v[k].y), fmaxf(v[k].z, v[k].w)));

        float s0 = 0.f, s1 = 0.f, s2 = 0.f, s3 = 0.f;   // 4 chains for ILP
#pragma unroll
        for (int k = 0; k < VPT; ++k) {
            v[k].x = sigt(v[k].x, ch); s0 += v[k].x;
            v[k].y = sigt(v[k].y, ch); s1 += v[k].y;
            v[k].z = sigt(v[k].z, ch); s2 += v[k].z;
            v[k].w = sigt(v[k].w, ch); s3 += v[k].w;
        }
        float sum = (s0 + s1) + (s2 + s3);

        // ---- reduction; next-row TMA issued at the first barrier ----
#pragma unroll
        for (int o = 16; o > 0; o >>= 1) {
            sum += __shfl_xor_sync(0xffffffffu, sum, o);
            mxx = fmaxf(mxx, __shfl_xor_sync(0xffffffffu, mxx, o));
        }
        if ((tid & 31) == 0) { reds[tid >> 5] = sum; redm[tid >> 5] = mxx; }
        __syncthreads();                         // all warps done reading buf4
        const int  rn = r + GRID;
        const bool has_next = rn < B;
        if (tid == 0 && has_next) {
            mbar_expect_tx(mbar, BUF_BYTES);
            bulk_ld(bufa, scores + (size_t)rn * T_DIM, BUF_BYTES, mbar);
        }
        if (tid < 32) {
            float s = reds[tid];
            float m = redm[tid];
#pragma unroll
            for (int o = 16; o > 0; o >>= 1) {
                s += __shfl_xor_sync(0xffffffffu, s, o);
                m = fmaxf(m, __shfl_xor_sync(0xffffffffu, m, o));
            }
            if (tid == 0) {
                const float b     = fmaxf(s, 1e-6f);
                const float scale = fminf(K_SEL / b, 1.0f);
                // ymax bound for COMPUTED y's: sigt(max x) + margin covering
                // tanh.approx non-monotonicity (<= 2*max_err ~ 1e-3).
                const float ymax_b = sigt(m, ch) + 2e-3f;
                s_scale = scale;
                s_fast  = (2.0f * scale * ymax_b <= 1.0f) ? 1 : 0;
            }
        }
        __syncthreads();
        const float scale = s_scale;
        float4* dst4 = reinterpret_cast<float4*>(out) + (size_t)r * (T_DIM / 4);

#pragma unroll
        for (int k = 0; k < VPT; ++k) {
            v[k].x *= scale; v[k].y *= scale; v[k].z *= scale; v[k].w *= scale;
        }

        if (s_fast) {
            // ---- FAST PATH: damping is the identity -> store from registers ----
            if (tid == 0) v[0].x = 0.0f;                 // y[:,0] = 0
#pragma unroll
            for (int k = 0; k < VPT; ++k) __stcs(dst4 + tid + k * NT, v[k]);
        } else {
            // ---- SLOW PATH (exact): chunked recompute in separate ys region ----
            float* dst = reinterpret_cast<float*>(dst4);
            for (int c = 0; c < T_DIM / CHUNK; ++c) {
                const int k0 = 2 * c, k1 = 2 * c + 1, kh = (2 * c + 2) & (VPT - 1);
                float4* ys4 = reinterpret_cast<float4*>(ys);
                ys4[tid]      = v[k0];
                ys4[NT + tid] = v[k1];
                if (tid < 3) ys4[2 * NT + tid] = v[kh];  // halo (wraps via mask)
                __syncthreads();

                float a[CPT + 10];
                const int st = CPT * tid;
#pragma unroll
                for (int j = 0; j < CPT + 10; ++j) a[j] = ys[st + j];
#pragma unroll
                for (int j = 0; j < CPT + 9; ++j) {      // d=1
                    const float t = a[j] + a[j + 1];
                    a[j] *= fminf(__fdividef(2.0f, 1.0f + t), 1.0f);
                }
#pragma unroll
                for (int j = 0; j < CPT + 7; ++j) {      // d=2
                    const float t = a[j] + a[j + 2];
                    a[j] *= fminf(__fdividef(2.0f, 1.0f + t), 1.0f);
                }
#pragma unroll
                for (int j = 0; j < CPT + 4; ++j) {      // d=3
                    const float t = a[j] + a[j + 3];
                    a[j] *= fminf(__fdividef(2.0f, 1.0f + t), 1.0f);
                }
#pragma unroll
                for (int j = 0; j < CPT; ++j) {          // d=4
                    const float t = a[j] + a[j + 4];
                    a[j] *= fminf(__fdividef(2.0f, 1.0f + t), 1.0f);
                }
                if (c == 0 && tid == 0) a[0] = 0.0f;     // y[:,0] = 0
#pragma unroll
                for (int j = 0; j < CPT; ++j) dst[c * CHUNK + st + j] = a[j];
                __syncthreads();
            }
        }

        if (!has_next) break;
        r = rn;
        parity ^= 1u;
    }
}

extern "C" void kernel_launch(void* const* d_in, const int* in_sizes, int n_in,
                              void* d_out, int out_size)
{
    // metadata order: scores [B,T] fp32, log_temperature scalar fp32 (pick by size)
    const float* scores;
    const float* log_temp;
    int n_scores;
    if (in_sizes[0] > in_sizes[1]) {
        scores = (const float*)d_in[0]; log_temp = (const float*)d_in[1];
        n_scores = in_sizes[0];
    } else {
        scores = (const float*)d_in[1]; log_temp = (const float*)d_in[0];
        n_scores = in_sizes[1];
    }
    const int B = n_scores / T_DIM;               // 512
    const int grid = (B < GRID) ? B : GRID;

    cudaFuncSetAttribute(fused_tanh,
                         cudaFuncAttributeMaxDynamicSharedMemorySize, DYN_SMEM);
    fused_tanh<<<grid, NT, DYN_SMEM>>>(scores, log_temp, (float*)d_out, B);
}

// round 13
// speedup vs baseline: 1.1631x; 1.1631x over previous
#include <cuda_runtime.h>
#include <cuda_bf16.h>
#include <cstdint>

// DifferentiableSelector, persistent + 4-deep chunked TMA ring.
//  R11 post-mortem: single-buffer TMA exposed ~1us wait per row (all three
//  prior designs pinned at ~27-29us with nothing saturated). Now each row is
//  4 x 32KB chunks in a 4-buffer ring with per-buffer mbarriers; chunk q+4 is
//  issued the moment buffer q&3 is drained, so the read stream crosses row
//  boundaries and never stalls. Stores are fire-and-forget and overlap the
//  next row's reads.
//  sigmoid(z) = 0.5*tanh.approx(z/2)+0.5 (3 ops/elem; rel_err 1.7e-6 in R11).
//  Identity-damping proof: raw-score max -> ymax bound (+2e-3 margin for the
//  approx); 2*scale*ymax <= 1 => every factor min(2/(1+a+b),1) == 1 exactly
//  -> fast path stores y*scale straight from registers.
//  Exact chunked slow path retained for arbitrary inputs.

static constexpr int   T_DIM = 32768;
static constexpr int   NT    = 1024;
static constexpr int   VPT   = T_DIM / NT / 4;   // 8 float4 per thread
static constexpr int   GRID  = 128;              // 512 rows / 128 = 4 rows/CTA
static constexpr float K_SEL = 64.0f;

static constexpr int CHUNK_E  = 8192;            // elements per chunk
static constexpr int CHUNK_B  = CHUNK_E * 4;     // 32 KB
static constexpr int NBUF     = 4;               // ring depth
// slow-path staging: 4 chunks of 8192 elements, halo 10 (use 12 = 3 float4)
static constexpr int CPT      = CHUNK_E / NT;    // 8 contiguous elems/thread
static constexpr int DYN_SMEM = NBUF * CHUNK_B + (CHUNK_E + 12) * 4;  // 163888

__device__ __forceinline__ float tanh_approx(float x) {
    float r; asm("tanh.approx.f32 %0, %1;" : "=f"(r) : "f"(x)); return r;
}
__device__ __forceinline__ uint32_t smem_u32(const void* p) {
    uint32_t a;
    asm("{ .reg .u64 t; cvta.to.shared.u64 t, %1; cvt.u32.u64 %0, t; }"
        : "=r"(a) : "l"(p));
    return a;
}
__device__ __forceinline__ void mbar_init(uint32_t mbar, uint32_t cnt) {
    asm volatile("mbarrier.init.shared.b64 [%0], %1;" :: "r"(mbar), "r"(cnt) : "memory");
}
__device__ __forceinline__ void mbar_expect_tx(uint32_t mbar, uint32_t bytes) {
    asm volatile("mbarrier.arrive.expect_tx.shared.b64 _, [%0], %1;"
                 :: "r"(mbar), "r"(bytes) : "memory");
}
__device__ __forceinline__ void bulk_ld(uint32_t dst_smem, const void* src,
                                        uint32_t bytes, uint32_t mbar) {
    asm volatile(
        "cp.async.bulk.shared::cta.global.mbarrier::complete_tx::bytes [%0], [%1], %2, [%3];"
        :: "r"(dst_smem), "l"(src), "r"(bytes), "r"(mbar) : "memory");
}
__device__ __forceinline__ void mbar_wait(uint32_t mbar, uint32_t parity) {
    asm volatile(
        "{\n\t"
        ".reg .pred P;\n\t"
        "WAIT_%=:\n\t"
        "mbarrier.try_wait.parity.acquire.cta.shared::cta.b64 P, [%0], %1, 0x989680;\n\t"
        "@P bra.uni DONE_%=;\n\t"
        "bra.uni WAIT_%=;\n\t"
        "DONE_%=:\n\t"
        "}" :: "r"(mbar), "r"(parity) : "memory");
}

// sigmoid(x/temp) = 0.5*tanh(x*ch)+0.5, ch = 0.5/temp.
__device__ __forceinline__ float sigt(float x, float ch) {
    return fmaf(0.5f, tanh_approx(x * ch), 0.5f);
}

__global__ __launch_bounds__(NT, 1)
void fused_ring(const float* __restrict__ scores,
                const float* __restrict__ log_temp,
                float* __restrict__ out, int B)
{
    extern __shared__ __align__(16) float dsm[];
    float*  ys = dsm + NBUF * CHUNK_E;            // slow-path staging
    __shared__ float reds[32], redm[32];
    __shared__ float s_scale;
    __shared__ int   s_fast;
    __shared__ __align__(8) uint64_t mbar_storage[NBUF];

    const int tid = threadIdx.x;
    const int bid = blockIdx.x;
    uint32_t mb[NBUF];
#pragma unroll
    for (int i = 0; i < NBUF; ++i) mb[i] = smem_u32(&mbar_storage[i]);
    const uint32_t bufa = smem_u32(dsm);

    float temp = __expf(log_temp[0]);
    temp = fminf(fmaxf(temp, 0.1f), 10.0f);
    const float ch = __fdividef(0.5f, temp);

    // rows for this CTA: bid, bid+GRID, ... ; chunk stream q = 0..4*nrows-1,
    // row(q) = bid + (q>>2)*GRID, chunk-in-row = buffer = q&3.
    const int nrows   = (B - bid + GRID - 1) / GRID;
    const int nchunks = 4 * nrows;

    if (tid == 0) {
#pragma unroll
        for (int i = 0; i < NBUF; ++i) mbar_init(mb[i], 1);
    }
    __syncthreads();
    if (tid == 0) {
#pragma unroll
        for (int q = 0; q < NBUF; ++q) {
            if (q < nchunks) {
                const int row = bid + (q >> 2) * GRID;
                mbar_expect_tx(mb[q], CHUNK_B);
                bulk_ld(bufa + q * CHUNK_B,
                        scores + (size_t)row * T_DIM + (q & 3) * CHUNK_E,
                        CHUNK_B, mb[q]);
            }
        }
    }

    int q = 0;
    int r = bid;
    for (int ri = 0; ri < nrows; ++ri) {
        float4 v[VPT];
        float s0 = 0.f, s1 = 0.f, s2 = 0.f, s3 = 0.f;
        float mxx = -3.4e38f;

        // ---- consume 4 chunks; refill ring immediately after each drain ----
#pragma unroll
        for (int c = 0; c < 4; ++c, ++q) {
            const int b = q & 3;
            mbar_wait(mb[b], (q >> 2) & 1);
            const float4* cb4 = reinterpret_cast<const float4*>(dsm + b * CHUNK_E);
            float4 va = cb4[tid];
            float4 vb = cb4[tid + NT];
            __syncthreads();                       // buffer b drained by all warps
            const int qn = q + NBUF;
            if (tid == 0 && qn < nchunks) {
                const int rown = bid + (qn >> 2) * GRID;
                mbar_expect_tx(mb[b], CHUNK_B);
                bulk_ld(bufa + b * CHUNK_B,
                        scores + (size_t)rown * T_DIM + (qn & 3) * CHUNK_E,
                        CHUNK_B, mb[b]);
            }
            // raw max (monotone in x) + sigmoid + partial sums
            mxx = fmaxf(mxx, fmaxf(fmaxf(va.x, va.y), fmaxf(va.z, va.w)));
            mxx = fmaxf(mxx, fmaxf(fmaxf(vb.x, vb.y), fmaxf(vb.z, vb.w)));
            va.x = sigt(va.x, ch); s0 += va.x;
            va.y = sigt(va.y, ch); s1 += va.y;
            va.z = sigt(va.z, ch); s2 += va.z;
            va.w = sigt(va.w, ch); s3 += va.w;
            vb.x = sigt(vb.x, ch); s0 += vb.x;
            vb.y = sigt(vb.y, ch); s1 += vb.y;
            vb.z = sigt(vb.z, ch); s2 += vb.z;
            vb.w = sigt(vb.w, ch); s3 += vb.w;
            v[2 * c]     = va;                     // float4 idx tid + 2c*NT
            v[2 * c + 1] = vb;                     // float4 idx tid + (2c+1)*NT
        }
        float sum = (s0 + s1) + (s2 + s3);

        // ---- block reduction: sum (budget) + raw max (identity proof) ----
#pragma unroll
        for (int o = 16; o > 0; o >>= 1) {
            sum += __shfl_xor_sync(0xffffffffu, sum, o);
            mxx = fmaxf(mxx, __shfl_xor_sync(0xffffffffu, mxx, o));
        }
        if ((tid & 31) == 0) { reds[tid >> 5] = sum; redm[tid >> 5] = mxx; }
        __syncthreads();
        if (tid < 32) {
            float s = reds[tid];
            float m = redm[tid];
#pragma unroll
            for (int o = 16; o > 0; o >>= 1) {
                s += __shfl_xor_sync(0xffffffffu, s, o);
                m = fmaxf(m, __shfl_xor_sync(0xffffffffu, m, o));
            }
            if (tid == 0) {
                const float bb    = fmaxf(s, 1e-6f);
                const float scale = fminf(K_SEL / bb, 1.0f);
                const float ymax_b = sigt(m, ch) + 2e-3f;   // approx margin
                s_scale = scale;
                s_fast  = (2.0f * scale * ymax_b <= 1.0f) ? 1 : 0;
            }
        }
        __syncthreads();
        const float scale = s_scale;
        float4* dst4 = reinterpret_cast<float4*>(out) + (size_t)r * (T_DIM / 4);

#pragma unroll
        for (int k = 0; k < VPT; ++k) {
            v[k].x *= scale; v[k].y *= scale; v[k].z *= scale; v[k].w *= scale;
        }

        if (s_fast) {
            // ---- FAST PATH: damping is the identity -> store from registers ----
            if (tid == 0) v[0].x = 0.0f;           // y[row][0] = 0
#pragma unroll
            for (int k = 0; k < VPT; ++k) __stcs(dst4 + tid + k * NT, v[k]);
        } else {
            // ---- SLOW PATH (exact): chunked recompute in ys region ----
            float* dst = reinterpret_cast<float*>(dst4);
            for (int c = 0; c < 4; ++c) {
                const int k0 = 2 * c, k1 = 2 * c + 1, kh = (2 * c + 2) & (VPT - 1);
                float4* ys4 = reinterpret_cast<float4*>(ys);
                ys4[tid]      = v[k0];
                ys4[NT + tid] = v[k1];
                if (tid < 3) ys4[2 * NT + tid] = v[kh];  // halo (wraps via mask)
                __syncthreads();

                float a[CPT + 10];
                const int st = CPT * tid;
#pragma unroll
                for (int j = 0; j < CPT + 10; ++j) a[j] = ys[st + j];
#pragma unroll
                for (int j = 0; j < CPT + 9; ++j) {      // d=1
                    const float t = a[j] + a[j + 1];
                    a[j] *= fminf(__fdividef(2.0f, 1.0f + t), 1.0f);
                }
#pragma unroll
                for (int j = 0; j < CPT + 7; ++j) {      // d=2
                    const float t = a[j] + a[j + 2];
                    a[j] *= fminf(__fdividef(2.0f, 1.0f + t), 1.0f);
                }
#pragma unroll
                for (int j = 0; j < CPT + 4; ++j) {      // d=3
                    const float t = a[j] + a[j + 3];
                    a[j] *= fminf(__fdividef(2.0f, 1.0f + t), 1.0f);
                }
#pragma unroll
                for (int j = 0; j < CPT; ++j) {          // d=4
                    const float t = a[j] + a[j + 4];
                    a[j] *= fminf(__fdividef(2.0f, 1.0f + t), 1.0f);
                }
                if (c == 0 && tid == 0) a[0] = 0.0f;     // y[row][0] = 0
#pragma unroll
                for (int j = 0; j < CPT; ++j) dst[c * CHUNK_E + st + j] = a[j];
                __syncthreads();
            }
        }
        r += GRID;
    }
}

extern "C" void kernel_launch(void* const* d_in, const int* in_sizes, int n_in,
                              void* d_out, int out_size)
{
    // metadata order: scores [B,T] fp32, log_temperature scalar fp32 (pick by size)
    const float* scores;
    const float* log_temp;
    int n_scores;
    if (in_sizes[0] > in_sizes[1]) {
        scores = (const float*)d_in[0]; log_temp = (const float*)d_in[1];
        n_scores = in_sizes[0];
    } else {
        scores = (const float*)d_in[1]; log_temp = (const float*)d_in[0];
        n_scores = in_sizes[1];
    }
    const int B = n_scores / T_DIM;               // 512
    const int grid = (B < GRID) ? B : GRID;

    cudaFuncSetAttribute(fused_ring,
                         cudaFuncAttributeMaxDynamicSharedMemorySize, DYN_SMEM);
    fused_ring<<<grid, NT, DYN_SMEM>>>(scores, log_temp, (float*)d_out, B);
}

// round 15
// speedup vs baseline: 1.2672x; 1.0895x over previous
#include <cuda_runtime.h>
#include <cuda_bf16.h>
#include <cstdint>

// DifferentiableSelector, persistent + 4-deep chunked TMA ring +
// producer/consumer named-barrier handoff (no block-wide sync in the
// consume loop).
//  Buffer c holds chunk c of the current row (buffer index == chunk index);
//  parity = row-iteration & 1. After reading buffer c, consumer warps 0-30
//  issue a NON-BLOCKING bar.arrive (release: orders their LDS reads before
//  the arrive); warp 31 bar.sync's (acquire) and elects one lane to refill
//  buffer c with the NEXT row's chunk c. Consumers never block between
//  chunks, so compute flows across chunk boundaries; only the per-row
//  budget reduction synchronizes the block (2 barriers/row).
//  sigmoid(z) = 0.5*tanh.approx(z/2)+0.5 (3 ops/elem; rel_err 1.7e-6).
//  Identity-damping proof: raw-score max -> ymax bound (+2e-3 margin for
//  the approx); 2*scale*ymax <= 1 => every factor min(2/(1+a+b),1) == 1
//  exactly -> fast path stores y*scale straight from registers.
//  Exact chunked slow path retained for arbitrary inputs.

static constexpr int   T_DIM = 32768;
static constexpr int   NT    = 1024;
static constexpr int   VPT   = T_DIM / NT / 4;   // 8 float4 per thread
static constexpr int   GRID  = 128;              // 512 rows / 128 = 4 rows/CTA
static constexpr float K_SEL = 64.0f;

static constexpr int CHUNK_E  = 8192;            // elements per chunk
static constexpr int CHUNK_B  = CHUNK_E * 4;     // 32 KB
static constexpr int NBUF     = 4;               // ring depth = chunks per row
static constexpr int CPT      = CHUNK_E / NT;    // 8 (slow-path elems/thread)
static constexpr int DYN_SMEM = NBUF * CHUNK_B + (CHUNK_E + 12) * 4;  // 163888

__device__ __forceinline__ float tanh_approx(float x) {
    float r; asm("tanh.approx.f32 %0, %1;" : "=f"(r) : "f"(x)); return r;
}
__device__ __forceinline__ uint32_t smem_u32(const void* p) {
    uint32_t a;
    asm("{ .reg .u64 t; cvta.to.shared.u64 t, %1; cvt.u32.u64 %0, t; }"
        : "=r"(a) : "l"(p));
    return a;
}
__device__ __forceinline__ void mbar_init(uint32_t mbar, uint32_t cnt) {
    asm volatile("mbarrier.init.shared.b64 [%0], %1;" :: "r"(mbar), "r"(cnt) : "memory");
}
__device__ __forceinline__ void mbar_expect_tx(uint32_t mbar, uint32_t bytes) {
    asm volatile("mbarrier.arrive.expect_tx.shared.b64 _, [%0], %1;"
                 :: "r"(mbar), "r"(bytes) : "memory");
}
__device__ __forceinline__ void bulk_ld(uint32_t dst_smem, const void* src,
                                        uint32_t bytes, uint32_t mbar) {
    asm volatile(
        "cp.async.bulk.shared::cta.global.mbarrier::complete_tx::bytes [%0], [%1], %2, [%3];"
        :: "r"(dst_smem), "l"(src), "r"(bytes), "r"(mbar) : "memory");
}
__device__ __forceinline__ void mbar_wait(uint32_t mbar, uint32_t parity) {
    asm volatile(
        "{\n\t"
        ".reg .pred P;\n\t"
        "WAIT_%=:\n\t"
        "mbarrier.try_wait.parity.acquire.cta.shared::cta.b64 P, [%0], %1, 0x989680;\n\t"
        "@P bra.uni DONE_%=;\n\t"
        "bra.uni WAIT_%=;\n\t"
        "DONE_%=:\n\t"
        "}" :: "r"(mbar), "r"(parity) : "memory");
}
__device__ __forceinline__ void bar_arrive(int id) {
    asm volatile("bar.arrive %0, %1;" :: "r"(id), "r"(NT) : "memory");
}
__device__ __forceinline__ void bar_sync_id(int id) {
    asm volatile("bar.sync %0, %1;" :: "r"(id), "r"(NT) : "memory");
}

// sigmoid(x/temp) = 0.5*tanh(x*ch)+0.5, ch = 0.5/temp.
__device__ __forceinline__ float sigt(float x, float ch) {
    return fmaf(0.5f, tanh_approx(x * ch), 0.5f);
}

__global__ __launch_bounds__(NT, 1)
void fused_ring_pc(const float* __restrict__ scores,
                   const float* __restrict__ log_temp,
                   float* __restrict__ out, int B)
{
    extern __shared__ __align__(16) float dsm[];
    float*  ys = dsm + NBUF * CHUNK_E;            // slow-path staging
    __shared__ float reds[32], redm[32];
    __shared__ float s_scale;
    __shared__ int   s_fast;
    __shared__ __align__(8) uint64_t mbar_storage[NBUF];

    const int tid = threadIdx.x;
    const int wid = tid >> 5;
    const int bid = blockIdx.x;
    uint32_t mb[NBUF];
#pragma unroll
    for (int i = 0; i < NBUF; ++i) mb[i] = smem_u32(&mbar_storage[i]);
    const uint32_t bufa = smem_u32(dsm);

    float temp = __expf(log_temp[0]);
    temp = fminf(fmaxf(temp, 0.1f), 10.0f);
    const float ch = __fdividef(0.5f, temp);

    const int nrows = (B - bid + GRID - 1) / GRID;

    if (tid == 0) {
#pragma unroll
        for (int i = 0; i < NBUF; ++i) mbar_init(mb[i], 1);
    }
    __syncthreads();
    if (tid == 0) {                               // prologue: row 0's 4 chunks
#pragma unroll
        for (int c = 0; c < NBUF; ++c) {
            mbar_expect_tx(mb[c], CHUNK_B);
            bulk_ld(bufa + c * CHUNK_B,
                    scores + (size_t)bid * T_DIM + c * CHUNK_E,
                    CHUNK_B, mb[c]);
        }
    }

    int r = bid;
    for (int ri = 0; ri < nrows; ++ri) {
        const uint32_t parity = (uint32_t)(ri & 1);
        const bool refill = (ri + 1) < nrows;
        const float* nrow = scores + (size_t)(r + GRID) * T_DIM;

        float4 v[VPT];
        float s0 = 0.f, s1 = 0.f, s2 = 0.f, s3 = 0.f;
        float mxx = -3.4e38f;

        // ---- consume 4 chunks; arrive-based handoff, no block sync ----
#pragma unroll
        for (int c = 0; c < NBUF; ++c) {
            mbar_wait(mb[c], parity);
            const float4* cb4 = reinterpret_cast<const float4*>(dsm + c * CHUNK_E);
            float4 va = cb4[tid];
            float4 vb = cb4[tid + NT];
            if (wid != 31) {
                bar_arrive(c + 1);                 // release: reads done
            } else {
                bar_sync_id(c + 1);                // acquire: all reads done
                if (refill && (tid & 31) == 0) {
                    mbar_expect_tx(mb[c], CHUNK_B);
                    bulk_ld(bufa + c * CHUNK_B, nrow + c * CHUNK_E,
                            CHUNK_B, mb[c]);
                }
            }
            // raw max (monotone in x) + sigmoid + partial sums
            mxx = fmaxf(mxx, fmaxf(fmaxf(va.x, va.y), fmaxf(va.z, va.w)));
            mxx = fmaxf(mxx, fmaxf(fmaxf(vb.x, vb.y), fmaxf(vb.z, vb.w)));
            va.x = sigt(va.x, ch); s0 += va.x;
            va.y = sigt(va.y, ch); s1 += va.y;
            va.z = sigt(va.z, ch); s2 += va.z;
            va.w = sigt(va.w, ch); s3 += va.w;
            vb.x = sigt(vb.x, ch); s0 += vb.x;
            vb.y = sigt(vb.y, ch); s1 += vb.y;
            vb.z = sigt(vb.z, ch); s2 += vb.z;
            vb.w = sigt(vb.w, ch); s3 += vb.w;
            v[2 * c]     = va;                     // float4 idx tid + 2c*NT
            v[2 * c + 1] = vb;                     // float4 idx tid + (2c+1)*NT
        }
        float sum = (s0 + s1) + (s2 + s3);

        // ---- block reduction: sum (budget) + raw max (identity proof) ----
#pragma unroll
        for (int o = 16; o > 0; o >>= 1) {
            sum += __shfl_xor_sync(0xffffffffu, sum, o);
            mxx = fmaxf(mxx, __shfl_xor_sync(0xffffffffu, mxx, o));
        }
        if ((tid & 31) == 0) { reds[wid] = sum; redm[wid] = mxx; }
        __syncthreads();
        if (tid < 32) {
            float s = reds[tid];
            float m = redm[tid];
#pragma unroll
            for (int o = 16; o > 0; o >>= 1) {
                s += __shfl_xor_sync(0xffffffffu, s, o);
                m = fmaxf(m, __shfl_xor_sync(0xffffffffu, m, o));
            }
            if (tid == 0) {
                const float bb    = fmaxf(s, 1e-6f);
                const float scale = fminf(K_SEL / bb, 1.0f);
                const float ymax_b = sigt(m, ch) + 2e-3f;   // approx margin
                s_scale = scale;
                s_fast  = (2.0f * scale * ymax_b <= 1.0f) ? 1 : 0;
            }
        }
        __syncthreads();
        const float scale = s_scale;
        float4* dst4 = reinterpret_cast<float4*>(out) + (size_t)r * (T_DIM / 4);

#pragma unroll
        for (int k = 0; k < VPT; ++k) {
            v[k].x *= scale; v[k].y *= scale; v[k].z *= scale; v[k].w *= scale;
        }

        if (s_fast) {
            // ---- FAST PATH: damping is the identity -> store from registers ----
            if (tid == 0) v[0].x = 0.0f;           // y[row][0] = 0
#pragma unroll
            for (int k = 0; k < VPT; ++k) __stcs(dst4 + tid + k * NT, v[k]);
        } else {
            // ---- SLOW PATH (exact): chunked recompute in ys region ----
            float* dst = reinterpret_cast<float*>(dst4);
            for (int c = 0; c < 4; ++c) {
                const int k0 = 2 * c, k1 = 2 * c + 1, kh = (2 * c + 2) & (VPT - 1);
                float4* ys4 = reinterpret_cast<float4*>(ys);
                ys4[tid]      = v[k0];
                ys4[NT + tid] = v[k1];
                if (tid < 3) ys4[2 * NT + tid] = v[kh];  // halo (wraps via mask)
                __syncthreads();

                float a[CPT + 10];
                const int st = CPT * tid;
#pragma unroll
                for (int j = 0; j < CPT + 10; ++j) a[j] = ys[st + j];
#pragma unroll
                for (int j = 0; j < CPT + 9; ++j) {      // d=1
                    const float t = a[j] + a[j + 1];
                    a[j] *= fminf(__fdividef(2.0f, 1.0f + t), 1.0f);
                }
#pragma unroll
                for (int j = 0; j < CPT + 7; ++j) {      // d=2
                    const float t = a[j] + a[j + 2];
                    a[j] *= fminf(__fdividef(2.0f, 1.0f + t), 1.0f);
                }
#pragma unroll
                for (int j = 0; j < CPT + 4; ++j) {      // d=3
                    const float t = a[j] + a[j + 3];
                    a[j] *= fminf(__fdividef(2.0f, 1.0f + t), 1.0f);
                }
#pragma unroll
                for (int j = 0; j < CPT; ++j) {          // d=4
                    const float t = a[j] + a[j + 4];
                    a[j] *= fminf(__fdividef(2.0f, 1.0f + t), 1.0f);
                }
                if (c == 0 && tid == 0) a[0] = 0.0f;     // y[row][0] = 0
#pragma unroll
                for (int j = 0; j < CPT; ++j) dst[c * CHUNK_E + st + j] = a[j];
                __syncthreads();
            }
        }
        r += GRID;
    }
}

extern "C" void kernel_launch(void* const* d_in, const int* in_sizes, int n_in,
                              void* d_out, int out_size)
{
    // metadata order: scores [B,T] fp32, log_temperature scalar fp32 (pick by size)
    const float* scores;
    const float* log_temp;
    int n_scores;
    if (in_sizes[0] > in_sizes[1]) {
        scores = (const float*)d_in[0]; log_temp = (const float*)d_in[1];
        n_scores = in_sizes[0];
    } else {
        scores = (const float*)d_in[1]; log_temp = (const float*)d_in[0];
        n_scores = in_sizes[1];
    }
    const int B = n_scores / T_DIM;               // 512
    const int grid = (B < GRID) ? B : GRID;

    cudaFuncSetAttribute(fused_ring_pc,
                         cudaFuncAttributeMaxDynamicSharedMemorySize, DYN_SMEM);
    fused_ring_pc<<<grid, NT, DYN_SMEM>>>(scores, log_temp, (float*)d_out, B);
}